// round 1
// baseline (speedup 1.0000x reference)
#include <cuda_runtime.h>
#include <cuda_bf16.h>

#define B_SZ   1024
#define DIN    1024
#define DHID   2048
#define TOPK   64
#define NCLAUSE 64
#define NACT   8

// ---------------- scratch (static device globals; no allocations) ----------
__device__ float  g_z[B_SZ * DHID];          // relu(x@W+b)  (8 MB)
__device__ float  g_R[DHID * NCLAUSE];       // (p-n)/(lit0+eps), layout [j][c] (512 KB)
__device__ double g_base[NCLAUSE];           // sum_j log(lit0+eps)
__device__ int    g_idx[B_SZ * TOPK];
__device__ float  g_gv[B_SZ * TOPK];         // f - f0 at selected indices

__device__ __forceinline__ float softplusf_(float x) {
    return (x > 0.f) ? (x + log1pf(expf(-x))) : log1pf(expf(x));
}

// ---------------- 1) per-(clause, j) tables + fp64 base log-sum -------------
__global__ void __launch_bounds__(256) precompute_kernel(
    const float* __restrict__ w_pos, const float* __restrict__ w_neg,
    const float* __restrict__ log_alpha, const float* __restrict__ beta) {
    int c = blockIdx.x;
    int t = threadIdx.x;
    double lsum = 0.0;
    for (int j = t; j < DHID; j += 256) {
        float wp = w_pos[c * DHID + j];
        float wn = w_neg[c * DHID + j];
        float m  = fmaxf(fmaxf(wp, wn), 0.f);
        float ep = expf(wp - m), en = expf(wn - m), e0 = expf(-m);
        float S  = ep + en + e0;
        float p  = ep / S, n = en / S;
        float a  = p - n;          // lit(f) = a*f + (1-p)
        float b  = 1.f - p;
        float al = softplusf_(log_alpha[j]) + 0.5f;
        float bt = beta[j];
        float f0 = 1.f / (1.f + expf(al * bt));     // sigmoid(-al*bt)
        float L0 = fmaf(a, f0, b) + 1e-8f;
        g_R[j * NCLAUSE + c] = a / L0;
        lsum += (double)logf(L0);
    }
    __shared__ double sred[256];
    sred[t] = lsum;
    __syncthreads();
    for (int s = 128; s > 0; s >>= 1) {
        if (t < s) sred[t] += sred[t + s];
        __syncthreads();
    }
    if (t == 0) g_base[c] = sred[0];
}

// ---------------- 2) fp32 SGEMM + bias + relu  (128x128x8, 8x8/thread) -----
__global__ void __launch_bounds__(256) gemm_relu_kernel(
    const float* __restrict__ X, const float* __restrict__ W,
    const float* __restrict__ bias) {
    __shared__ float As[8][132];   // +4 pad: conflict-free transposed stores
    __shared__ float Bs[8][128];
    int t  = threadIdx.x;
    int bm = blockIdx.y, bn = blockIdx.x;
    int tx = t & 15, ty = t >> 4;
    int arow = t >> 1,  acol = (t & 1) << 2;   // A tile: 128 rows x 8 k
    int brow = t >> 5,  bcol = (t & 31) << 2;  // B tile: 8 k x 128 n
    const float* Ag = X + (bm * 128 + arow) * DIN + acol;
    const float* Bg = W + brow * DHID + bn * 128 + bcol;

    float4 ra = *(const float4*)Ag;
    float4 rb = *(const float4*)Bg;

    float acc[8][8];
#pragma unroll
    for (int i = 0; i < 8; i++)
#pragma unroll
        for (int j = 0; j < 8; j++) acc[i][j] = 0.f;

    const int NKT = DIN / 8;
    for (int kt = 0; kt < NKT; kt++) {
        __syncthreads();
        As[acol + 0][arow] = ra.x;
        As[acol + 1][arow] = ra.y;
        As[acol + 2][arow] = ra.z;
        As[acol + 3][arow] = ra.w;
        *(float4*)&Bs[brow][bcol] = rb;
        __syncthreads();
        if (kt + 1 < NKT) {
            ra = *(const float4*)(Ag + (kt + 1) * 8);
            rb = *(const float4*)(Bg + (size_t)(kt + 1) * 8 * DHID);
        }
#pragma unroll
        for (int k = 0; k < 8; k++) {
            float a[8], b[8];
            *(float4*)&a[0] = *(const float4*)&As[k][ty * 8];
            *(float4*)&a[4] = *(const float4*)&As[k][ty * 8 + 4];
            *(float4*)&b[0] = *(const float4*)&Bs[k][tx * 8];
            *(float4*)&b[4] = *(const float4*)&Bs[k][tx * 8 + 4];
#pragma unroll
            for (int i = 0; i < 8; i++)
#pragma unroll
                for (int j = 0; j < 8; j++)
                    acc[i][j] = fmaf(a[i], b[j], acc[i][j]);
        }
    }
#pragma unroll
    for (int i = 0; i < 8; i++) {
        int row = bm * 128 + ty * 8 + i;
#pragma unroll
        for (int j4 = 0; j4 < 8; j4 += 4) {
            int col = bn * 128 + tx * 8 + j4;
            float4 v;
            v.x = fmaxf(acc[i][j4 + 0] + bias[col + 0], 0.f);
            v.y = fmaxf(acc[i][j4 + 1] + bias[col + 1], 0.f);
            v.z = fmaxf(acc[i][j4 + 2] + bias[col + 2], 0.f);
            v.w = fmaxf(acc[i][j4 + 3] + bias[col + 3], 0.f);
            *(float4*)&g_z[(size_t)row * DHID + col] = v;
        }
    }
}

// ---------------- 3) exact top-64 via 4-level radix select ------------------
__global__ void __launch_bounds__(256) topk_kernel(
    const float* __restrict__ log_alpha, const float* __restrict__ beta) {
    __shared__ unsigned sbits[DHID];
    __shared__ unsigned hist[256];
    __shared__ unsigned sh_d, sh_before;
    __shared__ unsigned cntA, cntB;
    int row = blockIdx.x;
    int t   = threadIdx.x;
    for (int i = t; i < DHID; i += 256)
        sbits[i] = __float_as_uint(g_z[(size_t)row * DHID + i]);   // >=0 => uint order
    if (t == 0) { cntA = 0; cntB = 0; }

    unsigned prefix = 0, pmask = 0;
    int need = TOPK;
    for (int lvl = 0; lvl < 4; lvl++) {
        int shift = 24 - lvl * 8;
        hist[t] = 0;
        __syncthreads();
        for (int i = t; i < DHID; i += 256) {
            unsigned b = sbits[i];
            if ((b & pmask) == prefix) atomicAdd(&hist[(b >> shift) & 255u], 1u);
        }
        __syncthreads();
        if (t == 0) {
            unsigned acc = 0;
            int d = 255;
            for (; d > 0; d--) { acc += hist[d]; if ((int)acc >= need) break; }
            if ((int)acc < need) acc += hist[0];   // d == 0 fall-through
            sh_d = (unsigned)d;
            sh_before = acc - hist[d];
        }
        __syncthreads();
        need  -= (int)sh_before;
        prefix |= (sh_d << shift);
        pmask  |= (255u << shift);
        __syncthreads();
    }
    unsigned T = prefix;      // exact bits of the 64th-largest value
    int r = need;             // how many ==T to take

    for (int i = t; i < DHID; i += 256) {
        unsigned b = sbits[i];
        int pos = -1;
        if (b > T) pos = (int)atomicAdd(&cntA, 1u);
        else if (b == T) {
            unsigned e = atomicAdd(&cntB, 1u);
            if (e < (unsigned)r) pos = (TOPK - r) + (int)e;
        }
        if (pos >= 0) {
            float v  = __uint_as_float(b);
            float al = softplusf_(log_alpha[i]) + 0.5f;
            float bt = beta[i];
            float f  = 1.f / (1.f + expf(-al * (v - bt)));
            float f0 = 1.f / (1.f + expf(al * bt));   // v==0 -> f==f0 bitwise -> g==0
            g_idx[row * TOPK + pos] = i;
            g_gv[row * TOPK + pos]  = f - f0;
        }
    }
}

// ---------------- 4) clause correction + fp64 sigmoid epilogue --------------
__global__ void __launch_bounds__(256) corr_kernel(
    const float* __restrict__ clause_weight, float* __restrict__ out) {
    int row = blockIdx.x;
    int t   = threadIdx.x;
    __shared__ int    sidx[TOPK];
    __shared__ float  sg[TOPK];
    __shared__ float  part[256];
    __shared__ double cl[NCLAUSE];
    if (t < TOPK) { sidx[t] = g_idx[row * TOPK + t]; sg[t] = g_gv[row * TOPK + t]; }
    __syncthreads();

    int c = t & 63;
    int grp = t >> 6;
    float acc = 0.f;
    for (int k = grp; k < TOPK; k += 4) {
        float u = g_R[sidx[k] * NCLAUSE + c] * sg[k];
        // log1p(u) = u - u^2/2 + u^3/3  (|u| < 2e-3 -> err < 1e-12)
        acc += u * fmaf(u, fmaf(u, 0.33333333f, -0.5f), 1.f);
    }
    part[t] = acc;
    __syncthreads();
    if (t < NCLAUSE) {
        float d = part[t] + part[t + 64] + part[t + 128] + part[t + 192];
        double logit = g_base[t] + (double)d + (double)clause_weight[t];
        cl[t] = 1.0 / (1.0 + exp(-logit));   // fp64: handles e^-93 (subnormal fp32) exactly
    }
    __syncthreads();
    if (t < NACT) {
        double s = 0.0;
#pragma unroll
        for (int l = 0; l < 8; l++) s += cl[t * 8 + l];
        out[row * NACT + t] = (float)s;      // single correctly-rounded f64->f32
    }
}

// ---------------- launch ----------------------------------------------------
extern "C" void kernel_launch(void* const* d_in, const int* in_sizes, int n_in,
                              void* d_out, int out_size) {
    const float* x         = (const float*)d_in[0];
    const float* W_enc     = (const float*)d_in[1];
    const float* b_enc     = (const float*)d_in[2];
    const float* log_alpha = (const float*)d_in[3];
    const float* beta      = (const float*)d_in[4];
    const float* w_pos     = (const float*)d_in[5];
    const float* w_neg     = (const float*)d_in[6];
    const float* cw        = (const float*)d_in[7];
    float* out = (float*)d_out;

    precompute_kernel<<<NCLAUSE, 256>>>(w_pos, w_neg, log_alpha, beta);
    gemm_relu_kernel<<<dim3(DHID / 128, B_SZ / 128), 256>>>(x, W_enc, b_enc);
    topk_kernel<<<B_SZ, 256>>>(log_alpha, beta);
    corr_kernel<<<B_SZ, 256>>>(cw, out);
}

// round 3
// speedup vs baseline: 1.5639x; 1.5639x over previous
#include <cuda_runtime.h>
#include <cuda_bf16.h>
#include <cstdint>

#define B_SZ   1024
#define DIN    1024
#define DHID   2048
#define TOPK   64
#define NCLAUSE 64
#define NACT   8

// ---------------- scratch (static device globals; no allocations) ----------
__device__ float  g_z[B_SZ * DHID];            // relu(x@W+b)  (8 MB)
__device__ float  g_R[DHID * NCLAUSE];         // (p-n)/(lit0+eps), layout [j][c]
__device__ double g_base[NCLAUSE];
__device__ int    g_idx[B_SZ * TOPK];
__device__ float  g_gv[B_SZ * TOPK];
__device__ __nv_bfloat16 g_xh[B_SZ * DIN];
__device__ __nv_bfloat16 g_xl[B_SZ * DIN];
__device__ __nv_bfloat16 g_wth[DHID * DIN];    // W^T hi, [n][k]
__device__ __nv_bfloat16 g_wtl[DHID * DIN];    // W^T lo

__device__ __forceinline__ float softplusf_(float x) {
    return (x > 0.f) ? (x + log1pf(expf(-x))) : log1pf(expf(x));
}
__device__ __forceinline__ uint32_t smem_to_u32(const void* p) {
    uint32_t a;
    asm("{ .reg .u64 t; cvta.to.shared.u64 t, %1; cvt.u32.u64 %0, t; }" : "=r"(a) : "l"(p));
    return a;
}
#define SWZ(b) ((b) ^ (((b) >> 3) & 0x70))
#define CP_ASYNC16(s, g) asm volatile("cp.async.cg.shared.global [%0], [%1], 16;" :: "r"(s), "l"(g))
#define CP_COMMIT()      asm volatile("cp.async.commit_group;" ::: "memory")
#define CP_WAIT(n)       asm volatile("cp.async.wait_group %0;" :: "n"(n) : "memory")

__device__ __forceinline__ void ldsm_x4(uint32_t& r0, uint32_t& r1, uint32_t& r2, uint32_t& r3,
                                        uint32_t addr) {
    asm volatile("ldmatrix.sync.aligned.m8n8.x4.shared.b16 {%0,%1,%2,%3}, [%4];"
                 : "=r"(r0), "=r"(r1), "=r"(r2), "=r"(r3) : "r"(addr));
}
__device__ __forceinline__ void mma16816(float* c, const uint32_t* a, uint32_t b0, uint32_t b1) {
    asm volatile("mma.sync.aligned.m16n8k16.row.col.f32.bf16.bf16.f32 "
                 "{%0,%1,%2,%3}, {%4,%5,%6,%7}, {%8,%9}, {%0,%1,%2,%3};"
                 : "+f"(c[0]), "+f"(c[1]), "+f"(c[2]), "+f"(c[3])
                 : "r"(a[0]), "r"(a[1]), "r"(a[2]), "r"(a[3]), "r"(b0), "r"(b1));
}

// =================== 0a) x -> (xh, xl) bf16 =================================
__global__ void __launch_bounds__(256) convert_x_kernel(const float* __restrict__ x) {
    int i = (blockIdx.x * 256 + threadIdx.x) * 4;
    float4 v = *(const float4*)(x + i);
    __nv_bfloat16 h0 = __float2bfloat16(v.x), h1 = __float2bfloat16(v.y);
    __nv_bfloat16 h2 = __float2bfloat16(v.z), h3 = __float2bfloat16(v.w);
    __nv_bfloat162 hi0 = {h0, h1}, hi1 = {h2, h3};
    __nv_bfloat162 lo0 = {__float2bfloat16(v.x - __bfloat162float(h0)),
                          __float2bfloat16(v.y - __bfloat162float(h1))};
    __nv_bfloat162 lo1 = {__float2bfloat16(v.z - __bfloat162float(h2)),
                          __float2bfloat16(v.w - __bfloat162float(h3))};
    *(__nv_bfloat162*)(g_xh + i)     = hi0;
    *(__nv_bfloat162*)(g_xh + i + 2) = hi1;
    *(__nv_bfloat162*)(g_xl + i)     = lo0;
    *(__nv_bfloat162*)(g_xl + i + 2) = lo1;
}

// =================== 0b) W -> W^T (hi, lo) bf16 =============================
__global__ void __launch_bounds__(256) transpose_w_kernel(const float* __restrict__ W) {
    __shared__ float tile[32][33];
    int n0 = blockIdx.x * 32, k0 = blockIdx.y * 32;
    int tx = threadIdx.x & 31, ty = threadIdx.x >> 5;
#pragma unroll
    for (int j = 0; j < 32; j += 8)
        tile[ty + j][tx] = W[(size_t)(k0 + ty + j) * DHID + n0 + tx];
    __syncthreads();
#pragma unroll
    for (int j = 0; j < 32; j += 8) {
        float v = tile[tx][ty + j];
        __nv_bfloat16 h = __float2bfloat16(v);
        g_wth[(size_t)(n0 + ty + j) * DIN + k0 + tx] = h;
        g_wtl[(size_t)(n0 + ty + j) * DIN + k0 + tx] =
            __float2bfloat16(v - __bfloat162float(h));
    }
}

// =================== 1) clause tables =======================================
__global__ void __launch_bounds__(256) precompute_kernel(
    const float* __restrict__ w_pos, const float* __restrict__ w_neg,
    const float* __restrict__ log_alpha, const float* __restrict__ beta) {
    int c = blockIdx.x;
    int t = threadIdx.x;
    double lsum = 0.0;
    for (int j = t; j < DHID; j += 256) {
        float wp = w_pos[c * DHID + j];
        float wn = w_neg[c * DHID + j];
        float m  = fmaxf(fmaxf(wp, wn), 0.f);
        float ep = expf(wp - m), en = expf(wn - m), e0 = expf(-m);
        float S  = ep + en + e0;
        float p  = ep / S, n = en / S;
        float a  = p - n;
        float b  = 1.f - p;
        float al = softplusf_(log_alpha[j]) + 0.5f;
        float bt = beta[j];
        float f0 = 1.f / (1.f + expf(al * bt));
        float L0 = fmaf(a, f0, b) + 1e-8f;
        g_R[j * NCLAUSE + c] = a / L0;
        lsum += (double)logf(L0);
    }
    __shared__ double sred[256];
    sred[t] = lsum;
    __syncthreads();
    for (int s = 128; s > 0; s >>= 1) {
        if (t < s) sred[t] += sred[t + s];
        __syncthreads();
    }
    if (t == 0) g_base[c] = sred[0];
}

// =================== 2) mma.sync bf16 GEMM (3-pass split) ===================
// 128x128 tile, BK=64, double-buffered cp.async, 8 warps (2m x 4n), 64x32/warp.
#define BK 64
#define TILE_BYTES (128 * BK * 2)          // 16 KB per tile
#define SM_A(b) ((b) * 2 * TILE_BYTES)
#define SM_B(b) ((b) * 2 * TILE_BYTES + TILE_BYTES)
#define GEMM_SMEM (4 * TILE_BYTES)         // 64 KB
#define NITER 48                            // 3 passes x 16 K-chunks of 64

__global__ void __launch_bounds__(256) gemm_mma_kernel(const float* __restrict__ bias) {
    extern __shared__ char smem[];
    uint32_t sbase = smem_to_u32(smem);
    int tid = threadIdx.x;
    int wid = tid >> 5, lane = tid & 31;
    int bn = blockIdx.x, bm = blockIdx.y;
    int wm = (wid >> 2) * 64;     // warp m offset in tile
    int wn = (wid & 3) * 32;      // warp n offset in tile

    // cp.async per-thread: 4 chunks of 16B per tile; idx -> (row, unit)
    int crow[4], cunit[4];
    uint32_t csoff[4];
#pragma unroll
    for (int u = 0; u < 4; u++) {
        int idx = u * 256 + tid;
        crow[u]  = idx >> 3;
        cunit[u] = idx & 7;
        csoff[u] = SWZ(crow[u] * 128 + cunit[u] * 16);
    }

    auto issue = [&](int it, int b) {
        int pass = it >> 4, kc = it & 15;
        const __nv_bfloat16* Ab = (pass == 1) ? g_xl : g_xh;
        const __nv_bfloat16* Bb = (pass == 2) ? g_wtl : g_wth;
        uint32_t sa = sbase + SM_A(b), sb = sbase + SM_B(b);
#pragma unroll
        for (int u = 0; u < 4; u++) {
            CP_ASYNC16(sa + csoff[u],
                       Ab + (size_t)(bm * 128 + crow[u]) * DIN + kc * 64 + cunit[u] * 8);
            CP_ASYNC16(sb + csoff[u],
                       Bb + (size_t)(bn * 128 + crow[u]) * DIN + kc * 64 + cunit[u] * 8);
        }
    };

    float acc[4][4][4];
#pragma unroll
    for (int i = 0; i < 4; i++)
#pragma unroll
        for (int j = 0; j < 4; j++)
#pragma unroll
            for (int r = 0; r < 4; r++) acc[i][j][r] = 0.f;

    issue(0, 0); CP_COMMIT();
    issue(1, 1); CP_COMMIT();

    // ldmatrix row index within tile (lane-dependent)
    int lrow = lane & 15;          // row within 16-row fragment
    int lhi  = lane >> 4;          // 16B-unit selector

    for (int it = 0; it < NITER; it++) {
        int b = it & 1;
        if (it < NITER - 1) { CP_WAIT(1); } else { CP_WAIT(0); }
        __syncthreads();
        uint32_t sa = sbase + SM_A(b), sb = sbase + SM_B(b);
#pragma unroll
        for (int ks = 0; ks < 4; ks++) {
            int unit = 2 * ks + lhi;                // 16B unit along K
            uint32_t afr[4][4], bfr[2][4];
#pragma unroll
            for (int mi = 0; mi < 4; mi++) {
                int row = wm + mi * 16 + lrow;
                ldsm_x4(afr[mi][0], afr[mi][1], afr[mi][2], afr[mi][3],
                        sa + SWZ(row * 128 + unit * 16));
            }
#pragma unroll
            for (int nj = 0; nj < 2; nj++) {
                int row = wn + nj * 16 + lrow;
                ldsm_x4(bfr[nj][0], bfr[nj][1], bfr[nj][2], bfr[nj][3],
                        sb + SWZ(row * 128 + unit * 16));
            }
            // bfr[nj]: r0=(n0-7,klo) r1=(n8-15,klo) r2=(n0-7,khi) r3=(n8-15,khi)
#pragma unroll
            for (int mi = 0; mi < 4; mi++) {
#pragma unroll
                for (int nj = 0; nj < 2; nj++) {
                    mma16816(acc[mi][nj * 2 + 0], afr[mi], bfr[nj][0], bfr[nj][2]);
                    mma16816(acc[mi][nj * 2 + 1], afr[mi], bfr[nj][1], bfr[nj][3]);
                }
            }
        }
        __syncthreads();
        if (it + 2 < NITER) { issue(it + 2, b); CP_COMMIT(); }
    }

    // epilogue: bias + relu, store to g_z
    int qrow = lane >> 2;          // 0..7
    int qcol = (lane & 3) * 2;
#pragma unroll
    for (int mi = 0; mi < 4; mi++) {
#pragma unroll
        for (int nj = 0; nj < 4; nj++) {
            int col = bn * 128 + wn + nj * 8 + qcol;
            float b0 = bias[col], b1 = bias[col + 1];
            int r0 = bm * 128 + wm + mi * 16 + qrow;
            float2 v0, v1;
            v0.x = fmaxf(acc[mi][nj][0] + b0, 0.f);
            v0.y = fmaxf(acc[mi][nj][1] + b1, 0.f);
            v1.x = fmaxf(acc[mi][nj][2] + b0, 0.f);
            v1.y = fmaxf(acc[mi][nj][3] + b1, 0.f);
            *(float2*)&g_z[(size_t)r0 * DHID + col]       = v0;
            *(float2*)&g_z[(size_t)(r0 + 8) * DHID + col] = v1;
        }
    }
}

// =================== 3) exact top-64 radix select ===========================
__global__ void __launch_bounds__(256) topk_kernel(
    const float* __restrict__ log_alpha, const float* __restrict__ beta) {
    __shared__ unsigned sbits[DHID];
    __shared__ unsigned hist[256];
    __shared__ unsigned sh_d, sh_before;
    __shared__ unsigned cntA, cntB;
    int row = blockIdx.x;
    int t   = threadIdx.x;
    for (int i = t; i < DHID; i += 256)
        sbits[i] = __float_as_uint(g_z[(size_t)row * DHID + i]);
    if (t == 0) { cntA = 0; cntB = 0; }

    unsigned prefix = 0, pmask = 0;
    int need = TOPK;
    for (int lvl = 0; lvl < 4; lvl++) {
        int shift = 24 - lvl * 8;
        hist[t] = 0;
        __syncthreads();
        for (int i = t; i < DHID; i += 256) {
            unsigned b = sbits[i];
            if ((b & pmask) == prefix) atomicAdd(&hist[(b >> shift) & 255u], 1u);
        }
        __syncthreads();
        if (t == 0) {
            unsigned acc = 0;
            int d = 255;
            for (; d > 0; d--) { acc += hist[d]; if ((int)acc >= need) break; }
            if ((int)acc < need) acc += hist[0];
            sh_d = (unsigned)d;
            sh_before = acc - hist[d];
        }
        __syncthreads();
        need  -= (int)sh_before;
        prefix |= (sh_d << shift);
        pmask  |= (255u << shift);
        __syncthreads();
    }
    unsigned T = prefix;
    int r = need;

    for (int i = t; i < DHID; i += 256) {
        unsigned b = sbits[i];
        int pos = -1;
        if (b > T) pos = (int)atomicAdd(&cntA, 1u);
        else if (b == T) {
            unsigned e = atomicAdd(&cntB, 1u);
            if (e < (unsigned)r) pos = (TOPK - r) + (int)e;
        }
        if (pos >= 0) {
            float v  = __uint_as_float(b);
            float al = softplusf_(log_alpha[i]) + 0.5f;
            float bt = beta[i];
            float f  = 1.f / (1.f + expf(-al * (v - bt)));
            float f0 = 1.f / (1.f + expf(al * bt));
            g_idx[row * TOPK + pos] = i;
            g_gv[row * TOPK + pos]  = f - f0;
        }
    }
}

// =================== 4) clause correction ===================================
__global__ void __launch_bounds__(256) corr_kernel(
    const float* __restrict__ clause_weight, float* __restrict__ out) {
    int row = blockIdx.x;
    int t   = threadIdx.x;
    __shared__ int    sidx[TOPK];
    __shared__ float  sg[TOPK];
    __shared__ float  part[256];
    __shared__ double cl[NCLAUSE];
    if (t < TOPK) { sidx[t] = g_idx[row * TOPK + t]; sg[t] = g_gv[row * TOPK + t]; }
    __syncthreads();

    int c = t & 63;
    int grp = t >> 6;
    float acc = 0.f;
    for (int k = grp; k < TOPK; k += 4) {
        float u = g_R[sidx[k] * NCLAUSE + c] * sg[k];
        acc += u * fmaf(u, fmaf(u, 0.33333333f, -0.5f), 1.f);
    }
    part[t] = acc;
    __syncthreads();
    if (t < NCLAUSE) {
        float d = part[t] + part[t + 64] + part[t + 128] + part[t + 192];
        double logit = g_base[t] + (double)d + (double)clause_weight[t];
        cl[t] = 1.0 / (1.0 + exp(-logit));
    }
    __syncthreads();
    if (t < NACT) {
        double s = 0.0;
#pragma unroll
        for (int l = 0; l < 8; l++) s += cl[t * 8 + l];
        out[row * NACT + t] = (float)s;
    }
}

// =================== launch =================================================
extern "C" void kernel_launch(void* const* d_in, const int* in_sizes, int n_in,
                              void* d_out, int out_size) {
    const float* x         = (const float*)d_in[0];
    const float* W_enc     = (const float*)d_in[1];
    const float* b_enc     = (const float*)d_in[2];
    const float* log_alpha = (const float*)d_in[3];
    const float* beta      = (const float*)d_in[4];
    const float* w_pos     = (const float*)d_in[5];
    const float* w_neg     = (const float*)d_in[6];
    const float* cw        = (const float*)d_in[7];
    float* out = (float*)d_out;

    static bool attr_set = false;
    if (!attr_set) {
        cudaFuncSetAttribute(gemm_mma_kernel,
                             cudaFuncAttributeMaxDynamicSharedMemorySize, GEMM_SMEM);
        attr_set = true;
    }

    convert_x_kernel<<<B_SZ * DIN / 1024, 256>>>(x);
    transpose_w_kernel<<<dim3(DHID / 32, DIN / 32), 256>>>(W_enc);
    precompute_kernel<<<NCLAUSE, 256>>>(w_pos, w_neg, log_alpha, beta);
    gemm_mma_kernel<<<dim3(DHID / 128, B_SZ / 128), 256, GEMM_SMEM>>>(b_enc);
    topk_kernel<<<B_SZ, 256>>>(log_alpha, beta);
    corr_kernel<<<B_SZ, 256>>>(cw, out);
}

// round 4
// speedup vs baseline: 1.6517x; 1.0561x over previous
#include <cuda_runtime.h>
#include <cuda_bf16.h>
#include <cstdint>

#define B_SZ   1024
#define DIN    1024
#define DHID   2048
#define TOPK   64
#define NCLAUSE 64
#define NACT   8

// ---------------- scratch (static device globals; no allocations) ----------
__device__ float  g_z[B_SZ * DHID];            // relu(x@W+b)
__device__ float  g_R[DHID * NCLAUSE];         // (p-n)/(lit0+eps), layout [j][c]
__device__ double g_base[NCLAUSE];
__device__ __nv_bfloat16 g_xh[B_SZ * DIN];
__device__ __nv_bfloat16 g_xl[B_SZ * DIN];
__device__ __nv_bfloat16 g_wth[DHID * DIN];    // W^T hi, [n][k]
__device__ __nv_bfloat16 g_wtl[DHID * DIN];    // W^T lo

__device__ __forceinline__ float softplusf_(float x) {
    return (x > 0.f) ? (x + log1pf(expf(-x))) : log1pf(expf(x));
}
__device__ __forceinline__ uint32_t smem_to_u32(const void* p) {
    uint32_t a;
    asm("{ .reg .u64 t; cvta.to.shared.u64 t, %1; cvt.u32.u64 %0, t; }" : "=r"(a) : "l"(p));
    return a;
}
#define SWZ(b) ((b) ^ (((b) >> 3) & 0x70))
#define CP_ASYNC16(s, g) asm volatile("cp.async.cg.shared.global [%0], [%1], 16;" :: "r"(s), "l"(g))
#define CP_COMMIT()      asm volatile("cp.async.commit_group;" ::: "memory")
#define CP_WAIT(n)       asm volatile("cp.async.wait_group %0;" :: "n"(n) : "memory")

__device__ __forceinline__ void ldsm_x4(uint32_t& r0, uint32_t& r1, uint32_t& r2, uint32_t& r3,
                                        uint32_t addr) {
    asm volatile("ldmatrix.sync.aligned.m8n8.x4.shared.b16 {%0,%1,%2,%3}, [%4];"
                 : "=r"(r0), "=r"(r1), "=r"(r2), "=r"(r3) : "r"(addr));
}
__device__ __forceinline__ void mma16816(float* c, const uint32_t* a, uint32_t b0, uint32_t b1) {
    asm volatile("mma.sync.aligned.m16n8k16.row.col.f32.bf16.bf16.f32 "
                 "{%0,%1,%2,%3}, {%4,%5,%6,%7}, {%8,%9}, {%0,%1,%2,%3};"
                 : "+f"(c[0]), "+f"(c[1]), "+f"(c[2]), "+f"(c[3])
                 : "r"(a[0]), "r"(a[1]), "r"(a[2]), "r"(a[3]), "r"(b0), "r"(b1));
}

// =================== 1) fused prep: convert_x | precompute | transpose ======
// grid: [0,1024) convert_x, [1024,1088) precompute, [1088,3136) transpose
#define PREP_BLOCKS (1024 + 64 + 2048)

__global__ void __launch_bounds__(256) prep_kernel(
    const float* __restrict__ x, const float* __restrict__ W,
    const float* __restrict__ w_pos, const float* __restrict__ w_neg,
    const float* __restrict__ log_alpha, const float* __restrict__ beta) {
    int blk = blockIdx.x;
    int t   = threadIdx.x;

    if (blk < 1024) {                       // ---- convert x -> (xh, xl) ----
        int i = (blk * 256 + t) * 4;
        float4 v = *(const float4*)(x + i);
        __nv_bfloat16 h0 = __float2bfloat16(v.x), h1 = __float2bfloat16(v.y);
        __nv_bfloat16 h2 = __float2bfloat16(v.z), h3 = __float2bfloat16(v.w);
        __nv_bfloat162 hi0 = {h0, h1}, hi1 = {h2, h3};
        __nv_bfloat162 lo0 = {__float2bfloat16(v.x - __bfloat162float(h0)),
                              __float2bfloat16(v.y - __bfloat162float(h1))};
        __nv_bfloat162 lo1 = {__float2bfloat16(v.z - __bfloat162float(h2)),
                              __float2bfloat16(v.w - __bfloat162float(h3))};
        *(__nv_bfloat162*)(g_xh + i)     = hi0;
        *(__nv_bfloat162*)(g_xh + i + 2) = hi1;
        *(__nv_bfloat162*)(g_xl + i)     = lo0;
        *(__nv_bfloat162*)(g_xl + i + 2) = lo1;
        return;
    }
    if (blk < 1088) {                       // ---- clause tables ----
        __shared__ double sred[256];
        int c = blk - 1024;
        double lsum = 0.0;
        for (int j = t; j < DHID; j += 256) {
            float wp = w_pos[c * DHID + j];
            float wn = w_neg[c * DHID + j];
            float m  = fmaxf(fmaxf(wp, wn), 0.f);
            float ep = expf(wp - m), en = expf(wn - m), e0 = expf(-m);
            float S  = ep + en + e0;
            float p  = ep / S, n = en / S;
            float a  = p - n;
            float b  = 1.f - p;
            float al = softplusf_(log_alpha[j]) + 0.5f;
            float bt = beta[j];
            float f0 = 1.f / (1.f + expf(al * bt));
            float L0 = fmaf(a, f0, b) + 1e-8f;
            g_R[j * NCLAUSE + c] = a / L0;
            lsum += (double)logf(L0);
        }
        sred[t] = lsum;
        __syncthreads();
        for (int s = 128; s > 0; s >>= 1) {
            if (t < s) sred[t] += sred[t + s];
            __syncthreads();
        }
        if (t == 0) g_base[c] = sred[0];
        return;
    }
    {                                       // ---- W -> W^T (hi, lo) ----
        __shared__ float tile[32][33];
        int bb = blk - 1088;                // 64 x 32 tiles
        int n0 = (bb & 63) * 32, k0 = (bb >> 6) * 32;
        int tx = t & 31, ty = t >> 5;
#pragma unroll
        for (int j = 0; j < 32; j += 8)
            tile[ty + j][tx] = W[(size_t)(k0 + ty + j) * DHID + n0 + tx];
        __syncthreads();
#pragma unroll
        for (int j = 0; j < 32; j += 8) {
            float v = tile[tx][ty + j];
            __nv_bfloat16 h = __float2bfloat16(v);
            g_wth[(size_t)(n0 + ty + j) * DIN + k0 + tx] = h;
            g_wtl[(size_t)(n0 + ty + j) * DIN + k0 + tx] =
                __float2bfloat16(v - __bfloat162float(h));
        }
    }
}

// =================== 2) mma.sync GEMM: 128x64 tile, 4-stage pipeline ========
// grid (32, 8) = 256 CTAs, 2 CTAs/SM. 8 warps as 4m x 2n, warp tile 32x32.
#define BK 64
#define A_BYTES (128 * BK * 2)             // 16 KB
#define B_BYTES (64 * BK * 2)              // 8 KB
#define STAGE_BYTES (A_BYTES + B_BYTES)    // 24 KB
#define NSTAGE 4
#define GEMM_SMEM (NSTAGE * STAGE_BYTES)   // 96 KB
#define NITER 48                            // 3 passes x 16 K-chunks

__global__ void __launch_bounds__(256, 2) gemm_mma_kernel(const float* __restrict__ bias) {
    extern __shared__ char smem[];
    uint32_t sbase = smem_to_u32(smem);
    int tid = threadIdx.x;
    int wid = tid >> 5, lane = tid & 31;
    int bn = blockIdx.x, bm = blockIdx.y;
    int wm = (wid >> 1) * 32;               // warp m offset (0,32,64,96)
    int wn = (wid & 1) * 32;                // warp n offset (0,32)

    // cp.async mapping: A = 1024 chunks (4/thread), B = 512 chunks (2/thread)
    int arow[4], aunit[4]; uint32_t asoff[4];
#pragma unroll
    for (int u = 0; u < 4; u++) {
        int idx = u * 256 + tid;
        arow[u] = idx >> 3; aunit[u] = idx & 7;
        asoff[u] = SWZ(arow[u] * 128 + aunit[u] * 16);
    }
    int brow[2], bunit[2]; uint32_t bsoff[2];
#pragma unroll
    for (int u = 0; u < 2; u++) {
        int idx = u * 256 + tid;
        brow[u] = idx >> 3; bunit[u] = idx & 7;
        bsoff[u] = SWZ(brow[u] * 128 + bunit[u] * 16);
    }

    auto issue = [&](int it) {
        if (it < NITER) {
            int pass = it >> 4, kc = it & 15;
            const __nv_bfloat16* Ab = (pass == 1) ? g_xl : g_xh;
            const __nv_bfloat16* Bb = (pass == 2) ? g_wtl : g_wth;
            uint32_t sa = sbase + (it & (NSTAGE - 1)) * STAGE_BYTES;
            uint32_t sb = sa + A_BYTES;
#pragma unroll
            for (int u = 0; u < 4; u++)
                CP_ASYNC16(sa + asoff[u],
                           Ab + (size_t)(bm * 128 + arow[u]) * DIN + kc * 64 + aunit[u] * 8);
#pragma unroll
            for (int u = 0; u < 2; u++)
                CP_ASYNC16(sb + bsoff[u],
                           Bb + (size_t)(bn * 64 + brow[u]) * DIN + kc * 64 + bunit[u] * 8);
        }
        CP_COMMIT();
    };

    float acc[2][4][4];
#pragma unroll
    for (int i = 0; i < 2; i++)
#pragma unroll
        for (int j = 0; j < 4; j++)
#pragma unroll
            for (int r = 0; r < 4; r++) acc[i][j][r] = 0.f;

    issue(0); issue(1); issue(2);

    int lrow = lane & 15;
    int lhi  = lane >> 4;

    for (int it = 0; it < NITER; it++) {
        CP_WAIT(2);
        __syncthreads();
        issue(it + 3);                       // overlaps with compute below
        uint32_t sa = sbase + (it & (NSTAGE - 1)) * STAGE_BYTES;
        uint32_t sb = sa + A_BYTES;
#pragma unroll
        for (int ks = 0; ks < 4; ks++) {
            int unit = 2 * ks + lhi;
            uint32_t afr[2][4], bfr[2][4];
#pragma unroll
            for (int mi = 0; mi < 2; mi++)
                ldsm_x4(afr[mi][0], afr[mi][1], afr[mi][2], afr[mi][3],
                        sa + SWZ((wm + mi * 16 + lrow) * 128 + unit * 16));
#pragma unroll
            for (int nf = 0; nf < 2; nf++)
                ldsm_x4(bfr[nf][0], bfr[nf][1], bfr[nf][2], bfr[nf][3],
                        sb + SWZ((wn + nf * 16 + lrow) * 128 + unit * 16));
#pragma unroll
            for (int mi = 0; mi < 2; mi++)
#pragma unroll
                for (int nf = 0; nf < 2; nf++) {
                    mma16816(acc[mi][nf * 2 + 0], afr[mi], bfr[nf][0], bfr[nf][2]);
                    mma16816(acc[mi][nf * 2 + 1], afr[mi], bfr[nf][1], bfr[nf][3]);
                }
        }
    }

    // epilogue: bias + relu -> g_z
    int qrow = lane >> 2;
    int qcol = (lane & 3) * 2;
#pragma unroll
    for (int mi = 0; mi < 2; mi++) {
#pragma unroll
        for (int nj = 0; nj < 4; nj++) {
            int col = bn * 64 + wn + nj * 8 + qcol;
            float b0 = bias[col], b1 = bias[col + 1];
            int r0 = bm * 128 + wm + mi * 16 + qrow;
            float2 v0, v1;
            v0.x = fmaxf(acc[mi][nj][0] + b0, 0.f);
            v0.y = fmaxf(acc[mi][nj][1] + b1, 0.f);
            v1.x = fmaxf(acc[mi][nj][2] + b0, 0.f);
            v1.y = fmaxf(acc[mi][nj][3] + b1, 0.f);
            *(float2*)&g_z[(size_t)r0 * DHID + col]       = v0;
            *(float2*)&g_z[(size_t)(r0 + 8) * DHID + col] = v1;
        }
    }
}

// =================== 3) fused topk + clause correction ======================
__global__ void __launch_bounds__(256) topk_corr_kernel(
    const float* __restrict__ log_alpha, const float* __restrict__ beta,
    const float* __restrict__ clause_weight, float* __restrict__ out) {
    __shared__ unsigned sbits[DHID];
    __shared__ unsigned hist[256];
    __shared__ unsigned sh_d, sh_before;
    __shared__ unsigned cntA, cntB;
    __shared__ int    sidx[TOPK];
    __shared__ float  sg[TOPK];
    __shared__ float  part[256];
    __shared__ double cl[NCLAUSE];
    int row = blockIdx.x;
    int t   = threadIdx.x;
    for (int i = t; i < DHID; i += 256)
        sbits[i] = __float_as_uint(g_z[(size_t)row * DHID + i]);
    if (t == 0) { cntA = 0; cntB = 0; }

    unsigned prefix = 0, pmask = 0;
    int need = TOPK;
    for (int lvl = 0; lvl < 4; lvl++) {
        int shift = 24 - lvl * 8;
        hist[t] = 0;
        __syncthreads();
        for (int i = t; i < DHID; i += 256) {
            unsigned b = sbits[i];
            if ((b & pmask) == prefix) atomicAdd(&hist[(b >> shift) & 255u], 1u);
        }
        __syncthreads();
        if (t == 0) {
            unsigned acc = 0;
            int d = 255;
            for (; d > 0; d--) { acc += hist[d]; if ((int)acc >= need) break; }
            if ((int)acc < need) acc += hist[0];
            sh_d = (unsigned)d;
            sh_before = acc - hist[d];
        }
        __syncthreads();
        need  -= (int)sh_before;
        prefix |= (sh_d << shift);
        pmask  |= (255u << shift);
        __syncthreads();
    }
    unsigned T = prefix;
    int r = need;

    for (int i = t; i < DHID; i += 256) {
        unsigned b = sbits[i];
        int pos = -1;
        if (b > T) pos = (int)atomicAdd(&cntA, 1u);
        else if (b == T) {
            unsigned e = atomicAdd(&cntB, 1u);
            if (e < (unsigned)r) pos = (TOPK - r) + (int)e;
        }
        if (pos >= 0) {
            float v  = __uint_as_float(b);
            float al = softplusf_(log_alpha[i]) + 0.5f;
            float bt = beta[i];
            float f  = 1.f / (1.f + expf(-al * (v - bt)));
            float f0 = 1.f / (1.f + expf(al * bt));
            sidx[pos] = i;
            sg[pos]   = f - f0;
        }
    }
    __syncthreads();

    // ---- clause correction ----
    int c = t & 63;
    int grp = t >> 6;
    float acc = 0.f;
    for (int k = grp; k < TOPK; k += 4) {
        float u = g_R[sidx[k] * NCLAUSE + c] * sg[k];
        acc += u * fmaf(u, fmaf(u, 0.33333333f, -0.5f), 1.f);   // log1p series
    }
    part[t] = acc;
    __syncthreads();
    if (t < NCLAUSE) {
        float d = part[t] + part[t + 64] + part[t + 128] + part[t + 192];
        double logit = g_base[t] + (double)d + (double)clause_weight[t];
        cl[t] = 1.0 / (1.0 + exp(-logit));
    }
    __syncthreads();
    if (t < NACT) {
        double s = 0.0;
#pragma unroll
        for (int l = 0; l < 8; l++) s += cl[t * 8 + l];
        out[row * NACT + t] = (float)s;
    }
}

// =================== launch =================================================
extern "C" void kernel_launch(void* const* d_in, const int* in_sizes, int n_in,
                              void* d_out, int out_size) {
    const float* x         = (const float*)d_in[0];
    const float* W_enc     = (const float*)d_in[1];
    const float* b_enc     = (const float*)d_in[2];
    const float* log_alpha = (const float*)d_in[3];
    const float* beta      = (const float*)d_in[4];
    const float* w_pos     = (const float*)d_in[5];
    const float* w_neg     = (const float*)d_in[6];
    const float* cw        = (const float*)d_in[7];
    float* out = (float*)d_out;

    static bool attr_set = false;
    if (!attr_set) {
        cudaFuncSetAttribute(gemm_mma_kernel,
                             cudaFuncAttributeMaxDynamicSharedMemorySize, GEMM_SMEM);
        attr_set = true;
    }

    prep_kernel<<<PREP_BLOCKS, 256>>>(x, W_enc, w_pos, w_neg, log_alpha, beta);
    gemm_mma_kernel<<<dim3(DHID / 64, B_SZ / 128), 256, GEMM_SMEM>>>(b_enc);
    topk_corr_kernel<<<B_SZ, 256>>>(log_alpha, beta, cw, out);
}

// round 5
// speedup vs baseline: 2.2636x; 1.3705x over previous
#include <cuda_runtime.h>
#include <cuda_bf16.h>
#include <cstdint>

#define B_SZ   1024
#define DIN    1024
#define DHID   2048
#define TOPK   64
#define NCLAUSE 64
#define NACT   8
#define WCAP   48          // boundary-window capacity
#define WDELTA 0.015f      // boundary half-width (>= ~8 sigma of 1-pass z error)

// ---------------- scratch (static device globals; no allocations) ----------
__device__ float  g_z[B_SZ * DHID];            // approx relu(x@W+b) (1-pass bf16)
__device__ float  g_R[DHID * NCLAUSE];
__device__ double g_base[NCLAUSE];
__device__ __nv_bfloat16 g_xh[B_SZ * DIN];
__device__ __nv_bfloat16 g_xl[B_SZ * DIN];
__device__ __nv_bfloat16 g_wth[DHID * DIN];    // W^T hi, [n][k]
__device__ __nv_bfloat16 g_wtl[DHID * DIN];    // W^T lo

__device__ __forceinline__ float softplusf_(float x) {
    return (x > 0.f) ? (x + log1pf(expf(-x))) : log1pf(expf(x));
}
__device__ __forceinline__ uint32_t smem_to_u32(const void* p) {
    uint32_t a;
    asm("{ .reg .u64 t; cvta.to.shared.u64 t, %1; cvt.u32.u64 %0, t; }" : "=r"(a) : "l"(p));
    return a;
}
#define SWZ(b) ((b) ^ (((b) >> 3) & 0x70))
#define CP_ASYNC16(s, g) asm volatile("cp.async.cg.shared.global [%0], [%1], 16;" :: "r"(s), "l"(g))
#define CP_COMMIT()      asm volatile("cp.async.commit_group;" ::: "memory")
#define CP_WAIT(n)       asm volatile("cp.async.wait_group %0;" :: "n"(n) : "memory")

__device__ __forceinline__ void ldsm_x4(uint32_t& r0, uint32_t& r1, uint32_t& r2, uint32_t& r3,
                                        uint32_t addr) {
    asm volatile("ldmatrix.sync.aligned.m8n8.x4.shared.b16 {%0,%1,%2,%3}, [%4];"
                 : "=r"(r0), "=r"(r1), "=r"(r2), "=r"(r3) : "r"(addr));
}
__device__ __forceinline__ void mma16816(float* c, const uint32_t* a, uint32_t b0, uint32_t b1) {
    asm volatile("mma.sync.aligned.m16n8k16.row.col.f32.bf16.bf16.f32 "
                 "{%0,%1,%2,%3}, {%4,%5,%6,%7}, {%8,%9}, {%0,%1,%2,%3};"
                 : "+f"(c[0]), "+f"(c[1]), "+f"(c[2]), "+f"(c[3])
                 : "r"(a[0]), "r"(a[1]), "r"(a[2]), "r"(a[3]), "r"(b0), "r"(b1));
}

// =================== 1) fused prep: convert_x | precompute | transpose ======
#define PREP_BLOCKS (1024 + 64 + 2048)

__global__ void __launch_bounds__(256) prep_kernel(
    const float* __restrict__ x, const float* __restrict__ W,
    const float* __restrict__ w_pos, const float* __restrict__ w_neg,
    const float* __restrict__ log_alpha, const float* __restrict__ beta) {
    int blk = blockIdx.x;
    int t   = threadIdx.x;

    if (blk < 1024) {                       // ---- convert x -> (xh, xl) ----
        int i = (blk * 256 + t) * 4;
        float4 v = *(const float4*)(x + i);
        __nv_bfloat16 h0 = __float2bfloat16(v.x), h1 = __float2bfloat16(v.y);
        __nv_bfloat16 h2 = __float2bfloat16(v.z), h3 = __float2bfloat16(v.w);
        __nv_bfloat162 hi0 = {h0, h1}, hi1 = {h2, h3};
        __nv_bfloat162 lo0 = {__float2bfloat16(v.x - __bfloat162float(h0)),
                              __float2bfloat16(v.y - __bfloat162float(h1))};
        __nv_bfloat162 lo1 = {__float2bfloat16(v.z - __bfloat162float(h2)),
                              __float2bfloat16(v.w - __bfloat162float(h3))};
        *(__nv_bfloat162*)(g_xh + i)     = hi0;
        *(__nv_bfloat162*)(g_xh + i + 2) = hi1;
        *(__nv_bfloat162*)(g_xl + i)     = lo0;
        *(__nv_bfloat162*)(g_xl + i + 2) = lo1;
        return;
    }
    if (blk < 1088) {                       // ---- clause tables ----
        __shared__ double sred[256];
        int c = blk - 1024;
        double lsum = 0.0;
        for (int j = t; j < DHID; j += 256) {
            float wp = w_pos[c * DHID + j];
            float wn = w_neg[c * DHID + j];
            float m  = fmaxf(fmaxf(wp, wn), 0.f);
            float ep = expf(wp - m), en = expf(wn - m), e0 = expf(-m);
            float S  = ep + en + e0;
            float p  = ep / S, n = en / S;
            float a  = p - n;
            float b  = 1.f - p;
            float al = softplusf_(log_alpha[j]) + 0.5f;
            float bt = beta[j];
            float f0 = 1.f / (1.f + expf(al * bt));
            float L0 = fmaf(a, f0, b) + 1e-8f;
            g_R[j * NCLAUSE + c] = a / L0;
            lsum += (double)logf(L0);
        }
        sred[t] = lsum;
        __syncthreads();
        for (int s = 128; s > 0; s >>= 1) {
            if (t < s) sred[t] += sred[t + s];
            __syncthreads();
        }
        if (t == 0) g_base[c] = sred[0];
        return;
    }
    {                                       // ---- W -> W^T (hi, lo) ----
        __shared__ float tile[32][33];
        int bb = blk - 1088;
        int n0 = (bb & 63) * 32, k0 = (bb >> 6) * 32;
        int tx = t & 31, ty = t >> 5;
#pragma unroll
        for (int j = 0; j < 32; j += 8)
            tile[ty + j][tx] = W[(size_t)(k0 + ty + j) * DHID + n0 + tx];
        __syncthreads();
#pragma unroll
        for (int j = 0; j < 32; j += 8) {
            float v = tile[tx][ty + j];
            __nv_bfloat16 h = __float2bfloat16(v);
            g_wth[(size_t)(n0 + ty + j) * DIN + k0 + tx] = h;
            g_wtl[(size_t)(n0 + ty + j) * DIN + k0 + tx] =
                __float2bfloat16(v - __bfloat162float(h));
        }
    }
}

// =================== 2) mma.sync GEMM: SINGLE bf16 pass =====================
#define BK 64
#define A_BYTES (128 * BK * 2)
#define B_BYTES (64 * BK * 2)
#define STAGE_BYTES (A_BYTES + B_BYTES)
#define NSTAGE 4
#define GEMM_SMEM (NSTAGE * STAGE_BYTES)   // 96 KB
#define NITER 16                            // 1 pass x 16 K-chunks

__global__ void __launch_bounds__(256, 2) gemm_mma_kernel(const float* __restrict__ bias) {
    extern __shared__ char smem[];
    uint32_t sbase = smem_to_u32(smem);
    int tid = threadIdx.x;
    int wid = tid >> 5, lane = tid & 31;
    int bn = blockIdx.x, bm = blockIdx.y;
    int wm = (wid >> 1) * 32;
    int wn = (wid & 1) * 32;

    int arow[4], aunit[4]; uint32_t asoff[4];
#pragma unroll
    for (int u = 0; u < 4; u++) {
        int idx = u * 256 + tid;
        arow[u] = idx >> 3; aunit[u] = idx & 7;
        asoff[u] = SWZ(arow[u] * 128 + aunit[u] * 16);
    }
    int brow[2], bunit[2]; uint32_t bsoff[2];
#pragma unroll
    for (int u = 0; u < 2; u++) {
        int idx = u * 256 + tid;
        brow[u] = idx >> 3; bunit[u] = idx & 7;
        bsoff[u] = SWZ(brow[u] * 128 + bunit[u] * 16);
    }

    auto issue = [&](int it) {
        if (it < NITER) {
            int kc = it;
            uint32_t sa = sbase + (it & (NSTAGE - 1)) * STAGE_BYTES;
            uint32_t sb = sa + A_BYTES;
#pragma unroll
            for (int u = 0; u < 4; u++)
                CP_ASYNC16(sa + asoff[u],
                           g_xh + (size_t)(bm * 128 + arow[u]) * DIN + kc * 64 + aunit[u] * 8);
#pragma unroll
            for (int u = 0; u < 2; u++)
                CP_ASYNC16(sb + bsoff[u],
                           g_wth + (size_t)(bn * 64 + brow[u]) * DIN + kc * 64 + bunit[u] * 8);
        }
        CP_COMMIT();
    };

    float acc[2][4][4];
#pragma unroll
    for (int i = 0; i < 2; i++)
#pragma unroll
        for (int j = 0; j < 4; j++)
#pragma unroll
            for (int r = 0; r < 4; r++) acc[i][j][r] = 0.f;

    issue(0); issue(1); issue(2);

    int lrow = lane & 15;
    int lhi  = lane >> 4;

    for (int it = 0; it < NITER; it++) {
        CP_WAIT(2);
        __syncthreads();
        issue(it + 3);
        uint32_t sa = sbase + (it & (NSTAGE - 1)) * STAGE_BYTES;
        uint32_t sb = sa + A_BYTES;
#pragma unroll
        for (int ks = 0; ks < 4; ks++) {
            int unit = 2 * ks + lhi;
            uint32_t afr[2][4], bfr[2][4];
#pragma unroll
            for (int mi = 0; mi < 2; mi++)
                ldsm_x4(afr[mi][0], afr[mi][1], afr[mi][2], afr[mi][3],
                        sa + SWZ((wm + mi * 16 + lrow) * 128 + unit * 16));
#pragma unroll
            for (int nf = 0; nf < 2; nf++)
                ldsm_x4(bfr[nf][0], bfr[nf][1], bfr[nf][2], bfr[nf][3],
                        sb + SWZ((wn + nf * 16 + lrow) * 128 + unit * 16));
#pragma unroll
            for (int mi = 0; mi < 2; mi++)
#pragma unroll
                for (int nf = 0; nf < 2; nf++) {
                    mma16816(acc[mi][nf * 2 + 0], afr[mi], bfr[nf][0], bfr[nf][2]);
                    mma16816(acc[mi][nf * 2 + 1], afr[mi], bfr[nf][1], bfr[nf][3]);
                }
        }
    }

    int qrow = lane >> 2;
    int qcol = (lane & 3) * 2;
#pragma unroll
    for (int mi = 0; mi < 2; mi++) {
#pragma unroll
        for (int nj = 0; nj < 4; nj++) {
            int col = bn * 64 + wn + nj * 8 + qcol;
            float b0 = bias[col], b1 = bias[col + 1];
            int r0 = bm * 128 + wm + mi * 16 + qrow;
            float2 v0, v1;
            v0.x = fmaxf(acc[mi][nj][0] + b0, 0.f);
            v0.y = fmaxf(acc[mi][nj][1] + b1, 0.f);
            v1.x = fmaxf(acc[mi][nj][2] + b0, 0.f);
            v1.y = fmaxf(acc[mi][nj][3] + b1, 0.f);
            *(float2*)&g_z[(size_t)r0 * DHID + col]       = v0;
            *(float2*)&g_z[(size_t)(r0 + 8) * DHID + col] = v1;
        }
    }
}

// =================== 3) topk (approx) + boundary refine + correction ========
__global__ void __launch_bounds__(256) topk_corr_kernel(
    const float* __restrict__ log_alpha, const float* __restrict__ beta,
    const float* __restrict__ bias,
    const float* __restrict__ clause_weight, float* __restrict__ out) {
    __shared__ unsigned sbits[DHID];           // 8 KB (approx z bits)
    __shared__ unsigned hist[256];
    __shared__ unsigned sh_d, sh_before;
    __shared__ unsigned cntA, cntW;
    __shared__ int    sidx[TOPK];
    __shared__ float  sg[TOPK];
    __shared__ float  part[256];
    __shared__ double cl[NCLAUSE];
    __shared__ int    widx[WCAP];
    __shared__ float  zwin[WCAP];
    __shared__ __nv_bfloat16 sxh[DIN], sxl[DIN];   // 4 KB
    int row = blockIdx.x;
    int t   = threadIdx.x;
    int wid = t >> 5, lane = t & 31;

    for (int i = t; i < DHID; i += 256)
        sbits[i] = __float_as_uint(g_z[(size_t)row * DHID + i]);
    // x row (hi/lo) for boundary refinement
    {
        const float4* xs = (const float4*)(g_xh + (size_t)row * DIN);
        const float4* xl = (const float4*)(g_xl + (size_t)row * DIN);
        if (t < 128) ((float4*)sxh)[t] = xs[t];
        else         ((float4*)sxl)[t - 128] = xl[t - 128];
    }
    if (t == 0) { cntA = 0; cntW = 0; }

    // ---- 4-level radix select on approx z: T = 64th-largest value ----
    unsigned prefix = 0, pmask = 0;
    int need = TOPK;
    for (int lvl = 0; lvl < 4; lvl++) {
        int shift = 24 - lvl * 8;
        hist[t] = 0;
        __syncthreads();
        for (int i = t; i < DHID; i += 256) {
            unsigned b = sbits[i];
            if ((b & pmask) == prefix) atomicAdd(&hist[(b >> shift) & 255u], 1u);
        }
        __syncthreads();
        if (t == 0) {
            unsigned acc = 0;
            int d = 255;
            for (; d > 0; d--) { acc += hist[d]; if ((int)acc >= need) break; }
            if ((int)acc < need) acc += hist[0];
            sh_d = (unsigned)d;
            sh_before = acc - hist[d];
        }
        __syncthreads();
        need  -= (int)sh_before;
        prefix |= (sh_d << shift);
        pmask  |= (255u << shift);
        __syncthreads();
    }
    float Tf  = __uint_as_float(prefix);
    float whi = Tf + WDELTA, wlo = Tf - WDELTA;

    // ---- classify: safe-selected (z > whi) vs boundary window ----
    for (int i = t; i < DHID; i += 256) {
        float za = __uint_as_float(sbits[i]);
        if (za > whi) {
            int pos = (int)atomicAdd(&cntA, 1u);
            float al = softplusf_(log_alpha[i]) + 0.5f;
            float bt = beta[i];
            float f  = 1.f / (1.f + expf(-al * (za - bt)));
            float f0 = 1.f / (1.f + expf(al * bt));
            sidx[pos] = i;
            sg[pos]   = f - f0;
        } else if (za >= wlo) {
            unsigned w = atomicAdd(&cntW, 1u);
            if (w < WCAP) widx[w] = i;
        }
    }
    __syncthreads();
    int A = (int)cntA;
    int W = (int)cntW; if (W > WCAP) W = WCAP;
    int need2 = TOPK - A;

    // ---- exact z for window candidates (3-term bf16 dot, warp per cand) ----
    for (int w = wid; w < W; w += 8) {
        int j = widx[w];
        const __nv_bfloat162* wh2 = (const __nv_bfloat162*)(g_wth + (size_t)j * DIN);
        const __nv_bfloat162* wl2 = (const __nv_bfloat162*)(g_wtl + (size_t)j * DIN);
        const __nv_bfloat162* xh2 = (const __nv_bfloat162*)sxh;
        const __nv_bfloat162* xl2 = (const __nv_bfloat162*)sxl;
        float s = 0.f;
        for (int p = lane; p < DIN / 2; p += 32) {
            __nv_bfloat162 a = xh2[p], b = wh2[p], c = xl2[p], d = wl2[p];
            float ax = __bfloat162float(a.x), ay = __bfloat162float(a.y);
            float bx = __bfloat162float(b.x), by = __bfloat162float(b.y);
            float cx = __bfloat162float(c.x), cy = __bfloat162float(c.y);
            float dx = __bfloat162float(d.x), dy = __bfloat162float(d.y);
            s = fmaf(ax, bx, s); s = fmaf(ay, by, s);         // xh*wh
            s = fmaf(ax, dx, s); s = fmaf(ay, dy, s);         // xh*wl
            s = fmaf(cx, bx, s); s = fmaf(cy, by, s);         // xl*wh
        }
#pragma unroll
        for (int o = 16; o > 0; o >>= 1) s += __shfl_xor_sync(0xFFFFFFFFu, s, o);
        if (lane == 0) zwin[w] = fmaxf(s + bias[j], 0.f);
    }
    __syncthreads();

    // ---- exact re-rank of window (deterministic tie-break by index) ----
    if (t < W) {
        float zk = zwin[t]; int jk = widx[t];
        int rho = 0;
        for (int m = 0; m < W; m++) {
            float zm = zwin[m];
            if (zm > zk || (zm == zk && widx[m] < jk)) rho++;
        }
        if (rho < need2) {
            float al = softplusf_(log_alpha[jk]) + 0.5f;
            float bt = beta[jk];
            float f  = 1.f / (1.f + expf(-al * (zk - bt)));
            float f0 = 1.f / (1.f + expf(al * bt));
            sidx[A + rho] = jk;
            sg[A + rho]   = f - f0;
        }
    }
    __syncthreads();

    // ---- clause correction (log1p series) + fp64 epilogue ----
    int c = t & 63;
    int grp = t >> 6;
    float acc = 0.f;
    for (int k = grp; k < TOPK; k += 4) {
        float u = g_R[sidx[k] * NCLAUSE + c] * sg[k];
        acc += u * fmaf(u, fmaf(u, 0.33333333f, -0.5f), 1.f);
    }
    part[t] = acc;
    __syncthreads();
    if (t < NCLAUSE) {
        float d = part[t] + part[t + 64] + part[t + 128] + part[t + 192];
        double logit = g_base[t] + (double)d + (double)clause_weight[t];
        cl[t] = 1.0 / (1.0 + exp(-logit));
    }
    __syncthreads();
    if (t < NACT) {
        double s = 0.0;
#pragma unroll
        for (int l = 0; l < 8; l++) s += cl[t * 8 + l];
        out[row * NACT + t] = (float)s;
    }
}

// =================== launch =================================================
extern "C" void kernel_launch(void* const* d_in, const int* in_sizes, int n_in,
                              void* d_out, int out_size) {
    const float* x         = (const float*)d_in[0];
    const float* W_enc     = (const float*)d_in[1];
    const float* b_enc     = (const float*)d_in[2];
    const float* log_alpha = (const float*)d_in[3];
    const float* beta      = (const float*)d_in[4];
    const float* w_pos     = (const float*)d_in[5];
    const float* w_neg     = (const float*)d_in[6];
    const float* cw        = (const float*)d_in[7];
    float* out = (float*)d_out;

    static bool attr_set = false;
    if (!attr_set) {
        cudaFuncSetAttribute(gemm_mma_kernel,
                             cudaFuncAttributeMaxDynamicSharedMemorySize, GEMM_SMEM);
        attr_set = true;
    }

    prep_kernel<<<PREP_BLOCKS, 256>>>(x, W_enc, w_pos, w_neg, log_alpha, beta);
    gemm_mma_kernel<<<dim3(DHID / 64, B_SZ / 128), 256, GEMM_SMEM>>>(b_enc);
    topk_corr_kernel<<<B_SZ, 256>>>(log_alpha, beta, b_enc, cw, out);
}

// round 6
// speedup vs baseline: 2.3893x; 1.0556x over previous
#include <cuda_runtime.h>
#include <cuda_bf16.h>
#include <cstdint>

#define B_SZ   1024
#define DIN    1024
#define DHID   2048
#define TOPK   64
#define NCLAUSE 64
#define NACT   8
#define WCAP   96
#define WDELTA 0.04f

// ---------------- scratch (static device globals; no allocations) ----------
__device__ __nv_bfloat16 g_zb[B_SZ * DHID];    // approx relu(x@W+b), bf16 (4 MB)
__device__ float  g_R[DHID * NCLAUSE];
__device__ double g_base[NCLAUSE];
__device__ float  g_alpha[DHID];               // softplus(log_alpha)+0.5
__device__ float  g_f0[DHID];                  // sigmoid(-alpha*beta)
__device__ __nv_bfloat16 g_xh[B_SZ * DIN];
__device__ __nv_bfloat16 g_xl[B_SZ * DIN];
__device__ __nv_bfloat16 g_wth[DHID * DIN];    // W^T hi, [n][k]
__device__ __nv_bfloat16 g_wtl[DHID * DIN];    // W^T lo

__device__ __forceinline__ float softplusf_(float x) {
    return (x > 0.f) ? (x + log1pf(expf(-x))) : log1pf(expf(x));
}
__device__ __forceinline__ float b2f(unsigned short u) {
    __nv_bfloat16_raw r; r.x = u;
    return __bfloat162float(__nv_bfloat16(r));
}
__device__ __forceinline__ uint32_t smem_to_u32(const void* p) {
    uint32_t a;
    asm("{ .reg .u64 t; cvta.to.shared.u64 t, %1; cvt.u32.u64 %0, t; }" : "=r"(a) : "l"(p));
    return a;
}
#define SWZ(b) ((b) ^ (((b) >> 3) & 0x70))
#define CP_ASYNC16(s, g) asm volatile("cp.async.cg.shared.global [%0], [%1], 16;" :: "r"(s), "l"(g))
#define CP_COMMIT()      asm volatile("cp.async.commit_group;" ::: "memory")
#define CP_WAIT(n)       asm volatile("cp.async.wait_group %0;" :: "n"(n) : "memory")

__device__ __forceinline__ void ldsm_x4(uint32_t& r0, uint32_t& r1, uint32_t& r2, uint32_t& r3,
                                        uint32_t addr) {
    asm volatile("ldmatrix.sync.aligned.m8n8.x4.shared.b16 {%0,%1,%2,%3}, [%4];"
                 : "=r"(r0), "=r"(r1), "=r"(r2), "=r"(r3) : "r"(addr));
}
__device__ __forceinline__ void mma16816(float* c, const uint32_t* a, uint32_t b0, uint32_t b1) {
    asm volatile("mma.sync.aligned.m16n8k16.row.col.f32.bf16.bf16.f32 "
                 "{%0,%1,%2,%3}, {%4,%5,%6,%7}, {%8,%9}, {%0,%1,%2,%3};"
                 : "+f"(c[0]), "+f"(c[1]), "+f"(c[2]), "+f"(c[3])
                 : "r"(a[0]), "r"(a[1]), "r"(a[2]), "r"(a[3]), "r"(b0), "r"(b1));
}

// =================== 1) fused prep ==========================================
// grid: [0,1024) convert_x | [1024,1088) clause tables | [1088,2112) W^T
#define PREP_BLOCKS (1024 + 64 + 1024)

__global__ void __launch_bounds__(256) prep_kernel(
    const float* __restrict__ x, const float* __restrict__ W,
    const float* __restrict__ w_pos, const float* __restrict__ w_neg,
    const float* __restrict__ log_alpha, const float* __restrict__ beta) {
    int blk = blockIdx.x;
    int t   = threadIdx.x;

    if (blk < 1024) {                       // ---- convert x -> (xh, xl) ----
        int i = (blk * 256 + t) * 4;
        float4 v = *(const float4*)(x + i);
        __nv_bfloat16 h0 = __float2bfloat16(v.x), h1 = __float2bfloat16(v.y);
        __nv_bfloat16 h2 = __float2bfloat16(v.z), h3 = __float2bfloat16(v.w);
        __nv_bfloat162 hi0 = {h0, h1}, hi1 = {h2, h3};
        __nv_bfloat162 lo0 = {__float2bfloat16(v.x - __bfloat162float(h0)),
                              __float2bfloat16(v.y - __bfloat162float(h1))};
        __nv_bfloat162 lo1 = {__float2bfloat16(v.z - __bfloat162float(h2)),
                              __float2bfloat16(v.w - __bfloat162float(h3))};
        *(__nv_bfloat162*)(g_xh + i)     = hi0;
        *(__nv_bfloat162*)(g_xh + i + 2) = hi1;
        *(__nv_bfloat162*)(g_xl + i)     = lo0;
        *(__nv_bfloat162*)(g_xl + i + 2) = lo1;
        return;
    }
    if (blk < 1088) {                       // ---- clause tables ----
        __shared__ double sred[256];
        int c = blk - 1024;
        double lsum = 0.0;
        for (int j = t; j < DHID; j += 256) {
            float wp = w_pos[c * DHID + j];
            float wn = w_neg[c * DHID + j];
            float m  = fmaxf(fmaxf(wp, wn), 0.f);
            float ep = expf(wp - m), en = expf(wn - m), e0 = expf(-m);
            float S  = ep + en + e0;
            float p  = ep / S, n = en / S;
            float a  = p - n;
            float b  = 1.f - p;
            float al = softplusf_(log_alpha[j]) + 0.5f;
            float bt = beta[j];
            float f0 = 1.f / (1.f + expf(al * bt));
            float L0 = fmaf(a, f0, b) + 1e-8f;
            g_R[j * NCLAUSE + c] = a / L0;
            if (c == 0) { g_alpha[j] = al; g_f0[j] = f0; }
            lsum += (double)logf(L0);
        }
        sred[t] = lsum;
        __syncthreads();
        for (int s = 128; s > 0; s >>= 1) {
            if (t < s) sred[t] += sred[t + s];
            __syncthreads();
        }
        if (t == 0) g_base[c] = sred[0];
        return;
    }
    {                                       // ---- W -> W^T (hi, lo), 32n x 64k tile ----
        __shared__ float tile[64][33];
        int bb = blk - 1088;
        int n0 = (bb & 63) * 32, k0 = (bb >> 6) * 64;
        int w = t >> 5, lane = t & 31;
#pragma unroll
        for (int j = 0; j < 8; j++) {
            int k = w + j * 8;
            tile[k][lane] = W[(size_t)(k0 + k) * DHID + n0 + lane];
        }
        __syncthreads();
#pragma unroll
        for (int nn = 0; nn < 4; nn++) {
            int n = w + nn * 8;
            float a0 = tile[2 * lane][n];
            float a1 = tile[2 * lane + 1][n];
            __nv_bfloat16 h0 = __float2bfloat16(a0), h1 = __float2bfloat16(a1);
            __nv_bfloat162 hp = {h0, h1};
            __nv_bfloat162 lp = {__float2bfloat16(a0 - __bfloat162float(h0)),
                                 __float2bfloat16(a1 - __bfloat162float(h1))};
            size_t off = (size_t)(n0 + n) * DIN + k0 + 2 * lane;
            *(__nv_bfloat162*)(g_wth + off) = hp;
            *(__nv_bfloat162*)(g_wtl + off) = lp;
        }
    }
}

// =================== 2) mma.sync GEMM: single bf16 pass =====================
#define BK 64
#define A_BYTES (128 * BK * 2)
#define B_BYTES (64 * BK * 2)
#define STAGE_BYTES (A_BYTES + B_BYTES)
#define NSTAGE 4
#define GEMM_SMEM (NSTAGE * STAGE_BYTES)   // 96 KB
#define NITER 16

__global__ void __launch_bounds__(256, 2) gemm_mma_kernel(const float* __restrict__ bias) {
    extern __shared__ char smem[];
    uint32_t sbase = smem_to_u32(smem);
    int tid = threadIdx.x;
    int wid = tid >> 5, lane = tid & 31;
    int bn = blockIdx.x, bm = blockIdx.y;
    int wm = (wid >> 1) * 32;
    int wn = (wid & 1) * 32;

    int arow[4], aunit[4]; uint32_t asoff[4];
#pragma unroll
    for (int u = 0; u < 4; u++) {
        int idx = u * 256 + tid;
        arow[u] = idx >> 3; aunit[u] = idx & 7;
        asoff[u] = SWZ(arow[u] * 128 + aunit[u] * 16);
    }
    int brow[2], bunit[2]; uint32_t bsoff[2];
#pragma unroll
    for (int u = 0; u < 2; u++) {
        int idx = u * 256 + tid;
        brow[u] = idx >> 3; bunit[u] = idx & 7;
        bsoff[u] = SWZ(brow[u] * 128 + bunit[u] * 16);
    }

    auto issue = [&](int it) {
        if (it < NITER) {
            int kc = it;
            uint32_t sa = sbase + (it & (NSTAGE - 1)) * STAGE_BYTES;
            uint32_t sb = sa + A_BYTES;
#pragma unroll
            for (int u = 0; u < 4; u++)
                CP_ASYNC16(sa + asoff[u],
                           g_xh + (size_t)(bm * 128 + arow[u]) * DIN + kc * 64 + aunit[u] * 8);
#pragma unroll
            for (int u = 0; u < 2; u++)
                CP_ASYNC16(sb + bsoff[u],
                           g_wth + (size_t)(bn * 64 + brow[u]) * DIN + kc * 64 + bunit[u] * 8);
        }
        CP_COMMIT();
    };

    float acc[2][4][4];
#pragma unroll
    for (int i = 0; i < 2; i++)
#pragma unroll
        for (int j = 0; j < 4; j++)
#pragma unroll
            for (int r = 0; r < 4; r++) acc[i][j][r] = 0.f;

    issue(0); issue(1); issue(2);

    int lrow = lane & 15;
    int lhi  = lane >> 4;

    for (int it = 0; it < NITER; it++) {
        CP_WAIT(2);
        __syncthreads();
        issue(it + 3);
        uint32_t sa = sbase + (it & (NSTAGE - 1)) * STAGE_BYTES;
        uint32_t sb = sa + A_BYTES;
#pragma unroll
        for (int ks = 0; ks < 4; ks++) {
            int unit = 2 * ks + lhi;
            uint32_t afr[2][4], bfr[2][4];
#pragma unroll
            for (int mi = 0; mi < 2; mi++)
                ldsm_x4(afr[mi][0], afr[mi][1], afr[mi][2], afr[mi][3],
                        sa + SWZ((wm + mi * 16 + lrow) * 128 + unit * 16));
#pragma unroll
            for (int nf = 0; nf < 2; nf++)
                ldsm_x4(bfr[nf][0], bfr[nf][1], bfr[nf][2], bfr[nf][3],
                        sb + SWZ((wn + nf * 16 + lrow) * 128 + unit * 16));
#pragma unroll
            for (int mi = 0; mi < 2; mi++)
#pragma unroll
                for (int nf = 0; nf < 2; nf++) {
                    mma16816(acc[mi][nf * 2 + 0], afr[mi], bfr[nf][0], bfr[nf][2]);
                    mma16816(acc[mi][nf * 2 + 1], afr[mi], bfr[nf][1], bfr[nf][3]);
                }
        }
    }

    int qrow = lane >> 2;
    int qcol = (lane & 3) * 2;
#pragma unroll
    for (int mi = 0; mi < 2; mi++) {
#pragma unroll
        for (int nj = 0; nj < 4; nj++) {
            int col = bn * 64 + wn + nj * 8 + qcol;
            float b0 = bias[col], b1 = bias[col + 1];
            int r0 = bm * 128 + wm + mi * 16 + qrow;
            __nv_bfloat162 p0, p1;
            p0.x = __float2bfloat16(fmaxf(acc[mi][nj][0] + b0, 0.f));
            p0.y = __float2bfloat16(fmaxf(acc[mi][nj][1] + b1, 0.f));
            p1.x = __float2bfloat16(fmaxf(acc[mi][nj][2] + b0, 0.f));
            p1.y = __float2bfloat16(fmaxf(acc[mi][nj][3] + b1, 0.f));
            *(__nv_bfloat162*)&g_zb[(size_t)r0 * DHID + col]       = p0;
            *(__nv_bfloat162*)&g_zb[(size_t)(r0 + 8) * DHID + col] = p1;
        }
    }
}

// =================== 3) topk (2-level bf16 radix) + refine + correction =====
__global__ void __launch_bounds__(256) topk_corr_kernel(
    const float* __restrict__ beta, const float* __restrict__ bias,
    const float* __restrict__ clause_weight, float* __restrict__ out) {
    __shared__ unsigned short sbits[DHID];     // 4 KB
    __shared__ unsigned hist[256];
    __shared__ unsigned sh_d, sh_before;
    __shared__ unsigned cntA, cntW;
    __shared__ int    sidx[TOPK];
    __shared__ float  sg[TOPK];
    __shared__ float  part[256];
    __shared__ double cl[NCLAUSE];
    __shared__ int    widx[WCAP];
    __shared__ float  zwin[WCAP];
    __shared__ __nv_bfloat16 sxh[DIN], sxl[DIN];
    int row = blockIdx.x;
    int t   = threadIdx.x;
    int wid = t >> 5, lane = t & 31;

    {   // load bf16 z row (packed) + x row hi/lo
        const unsigned* zr = (const unsigned*)(g_zb + (size_t)row * DHID);
        for (int i = t; i < DHID / 2; i += 256) {
            unsigned v = zr[i];
            sbits[2 * i]     = (unsigned short)(v & 0xFFFFu);
            sbits[2 * i + 1] = (unsigned short)(v >> 16);
        }
        const float4* xs = (const float4*)(g_xh + (size_t)row * DIN);
        const float4* xl = (const float4*)(g_xl + (size_t)row * DIN);
        if (t < 128) ((float4*)sxh)[t] = xs[t];
        else         ((float4*)sxl)[t - 128] = xl[t - 128];
    }
    if (t == 0) { cntA = 0; cntW = 0; }

    // ---- 2-level radix select on bf16 bits: T = 64th-largest ----
    unsigned prefix = 0, pmask = 0;
    int need = TOPK;
#pragma unroll
    for (int lvl = 0; lvl < 2; lvl++) {
        int shift = 8 - lvl * 8;
        hist[t] = 0;
        __syncthreads();
        for (int i = t; i < DHID; i += 256) {
            unsigned b = sbits[i];
            if ((b & pmask) == prefix) atomicAdd(&hist[(b >> shift) & 255u], 1u);
        }
        __syncthreads();
        if (t == 0) {
            unsigned acc = 0;
            int d = 255;
            for (; d > 0; d--) { acc += hist[d]; if ((int)acc >= need) break; }
            if ((int)acc < need) acc += hist[0];
            sh_d = (unsigned)d;
            sh_before = acc - hist[d];
        }
        __syncthreads();
        need  -= (int)sh_before;
        prefix |= (sh_d << shift);
        pmask  |= (255u << shift);
        __syncthreads();
    }
    float Tf  = b2f((unsigned short)prefix);
    float whi = Tf + WDELTA, wlo = Tf - WDELTA;

    // ---- classify: safe (za > whi) vs boundary window ----
    for (int i = t; i < DHID; i += 256) {
        float za = b2f(sbits[i]);
        if (za > whi) {
            int pos = (int)atomicAdd(&cntA, 1u);
            float al = g_alpha[i];
            float f  = 1.f / (1.f + expf(-al * (za - beta[i])));
            sidx[pos] = i;
            sg[pos]   = f - g_f0[i];
        } else if (za >= wlo) {
            unsigned w = atomicAdd(&cntW, 1u);
            if (w < WCAP) widx[w] = i;
        }
    }
    __syncthreads();
    int A = (int)cntA;
    int W = (int)cntW; if (W > WCAP) W = WCAP;
    int need2 = TOPK - A;

    // ---- exact z for window candidates (3-term bf16 dot, warp per cand) ----
    for (int w = wid; w < W; w += 8) {
        int j = widx[w];
        const __nv_bfloat162* wh2 = (const __nv_bfloat162*)(g_wth + (size_t)j * DIN);
        const __nv_bfloat162* wl2 = (const __nv_bfloat162*)(g_wtl + (size_t)j * DIN);
        const __nv_bfloat162* xh2 = (const __nv_bfloat162*)sxh;
        const __nv_bfloat162* xl2 = (const __nv_bfloat162*)sxl;
        float s = 0.f;
        for (int p = lane; p < DIN / 2; p += 32) {
            __nv_bfloat162 a = xh2[p], b = wh2[p], c = xl2[p], d = wl2[p];
            float ax = __bfloat162float(a.x), ay = __bfloat162float(a.y);
            float bx = __bfloat162float(b.x), by = __bfloat162float(b.y);
            float cx = __bfloat162float(c.x), cy = __bfloat162float(c.y);
            float dx = __bfloat162float(d.x), dy = __bfloat162float(d.y);
            s = fmaf(ax, bx, s); s = fmaf(ay, by, s);
            s = fmaf(ax, dx, s); s = fmaf(ay, dy, s);
            s = fmaf(cx, bx, s); s = fmaf(cy, by, s);
        }
#pragma unroll
        for (int o = 16; o > 0; o >>= 1) s += __shfl_xor_sync(0xFFFFFFFFu, s, o);
        if (lane == 0) zwin[w] = fmaxf(s + bias[j], 0.f);
    }
    __syncthreads();

    // ---- exact re-rank of window ----
    if (t < W) {
        float zk = zwin[t]; int jk = widx[t];
        int rho = 0;
        for (int m = 0; m < W; m++) {
            float zm = zwin[m];
            if (zm > zk || (zm == zk && widx[m] < jk)) rho++;
        }
        if (rho < need2) {
            float al = g_alpha[jk];
            float f  = 1.f / (1.f + expf(-al * (zk - beta[jk])));
            sidx[A + rho] = jk;
            sg[A + rho]   = f - g_f0[jk];
        }
    }
    __syncthreads();

    // ---- clause correction (log1p series) + fp64 epilogue ----
    int c = t & 63;
    int grp = t >> 6;
    float acc = 0.f;
    for (int k = grp; k < TOPK; k += 4) {
        float u = g_R[sidx[k] * NCLAUSE + c] * sg[k];
        acc += u * fmaf(u, fmaf(u, 0.33333333f, -0.5f), 1.f);
    }
    part[t] = acc;
    __syncthreads();
    if (t < NCLAUSE) {
        float d = part[t] + part[t + 64] + part[t + 128] + part[t + 192];
        double logit = g_base[t] + (double)d + (double)clause_weight[t];
        cl[t] = 1.0 / (1.0 + exp(-logit));
    }
    __syncthreads();
    if (t < NACT) {
        double s = 0.0;
#pragma unroll
        for (int l = 0; l < 8; l++) s += cl[t * 8 + l];
        out[row * NACT + t] = (float)s;
    }
}

// =================== launch =================================================
extern "C" void kernel_launch(void* const* d_in, const int* in_sizes, int n_in,
                              void* d_out, int out_size) {
    const float* x         = (const float*)d_in[0];
    const float* W_enc     = (const float*)d_in[1];
    const float* b_enc     = (const float*)d_in[2];
    const float* log_alpha = (const float*)d_in[3];
    const float* beta      = (const float*)d_in[4];
    const float* w_pos     = (const float*)d_in[5];
    const float* w_neg     = (const float*)d_in[6];
    const float* cw        = (const float*)d_in[7];
    float* out = (float*)d_out;

    static bool attr_set = false;
    if (!attr_set) {
        cudaFuncSetAttribute(gemm_mma_kernel,
                             cudaFuncAttributeMaxDynamicSharedMemorySize, GEMM_SMEM);
        attr_set = true;
    }

    prep_kernel<<<PREP_BLOCKS, 256>>>(x, W_enc, w_pos, w_neg, log_alpha, beta);
    gemm_mma_kernel<<<dim3(DHID / 64, B_SZ / 128), 256, GEMM_SMEM>>>(b_enc);
    topk_corr_kernel<<<B_SZ, 256>>>(beta, b_enc, cw, out);
}